// round 15
// baseline (speedup 1.0000x reference)
#include <cuda_runtime.h>
#include <cuda_fp16.h>
#include <cstdint>

// FAST attention (p=2 Taylor linear attention) as two unified feature GEMMs
// on HMMA fp16 (mma.sync m16n8k16, fp32 accum).  [R12 + ph2 pair-loads]
//   Phi[n,F]: F=0 -> 1, F=1..32 -> x_d, F=33..560 -> pair products
//   Phase 1: M3[F,e] = sum_n PhiK_w[n,F] * Vaug[n,e]   (A fp16 regs from
//            row-major k-stage; B fp16 smem + ldmatrix; ones-row constant)
//   combine: 8 n-partials -> one fp32 M3 (coalesced)
//   frag:    M3 -> pre-swizzled per-lane fp16 mma B-fragments
//   Phase 2: D[n,e]  = sum_F PhiQ[n,F] * M3[F,e]; out = D[:,0:32]/D[:,32]
//            A-fragments via common-operand PAIR loads (3 LDS not 4);
//            boundary pairs take a predicated 2-load fixup for v1.

#define NBH   32
#define NSEQ  4096
#define DD    32
#define FTOT  561
#define FPAD  576
#define ER    33
#define NPART 8

#define KSTR  140
#define BSTR  144
#define BROWS 32
#define BHALF (BROWS * BSTR)

__device__ uint32_t g_ptab4[640];
__device__ float    g_wtab[640];
__device__ uint2    g_ptab2[320];
__device__ float    g_M3p[NPART * NBH * ER * FPAD];
__device__ float    g_M3s[NBH * ER * FPAD];
__device__ uint2    g_M3frag[NBH * 36 * 5 * 32];

__device__ __forceinline__ uint32_t smem_u32(const void* p) {
    uint32_t a;
    asm("{ .reg .u64 t; cvta.to.shared.u64 t, %1; cvt.u32.u64 %0, t; }" : "=r"(a) : "l"(p));
    return a;
}
__device__ __forceinline__ uint32_t packH2(float v0, float v1) {
    uint32_t r;
    asm("cvt.rn.f16x2.f32 %0, %1, %2;" : "=r"(r) : "f"(v1), "f"(v0));
    return r;
}
__device__ __forceinline__ void ldm4(uint32_t b[4], uint32_t addr) {
    asm volatile("ldmatrix.sync.aligned.m8n8.x4.shared.b16 {%0,%1,%2,%3}, [%4];"
                 : "=r"(b[0]), "=r"(b[1]), "=r"(b[2]), "=r"(b[3]) : "r"(addr));
}
__device__ __forceinline__ void mmaH(float c[4], const uint32_t a[4], const uint32_t b[2]) {
    asm volatile("mma.sync.aligned.m16n8k16.row.col.f32.f16.f16.f32 "
                 "{%0,%1,%2,%3}, {%4,%5,%6,%7}, {%8,%9}, {%0,%1,%2,%3};"
                 : "+f"(c[0]), "+f"(c[1]), "+f"(c[2]), "+f"(c[3])
                 : "r"(a[0]), "r"(a[1]), "r"(a[2]), "r"(a[3]), "r"(b[0]), "r"(b[1]));
}
__device__ __forceinline__ float prod2(uint32_t pr, uint32_t ao, uint32_t bo) {
    float x, y;
    asm("ld.shared.f32 %0, [%1];" : "=f"(x) : "r"(pr + ao));
    asm("ld.shared.f32 %0, [%1];" : "=f"(y) : "r"(pr + bo));
    return x * y;
}
// pair A-fragment: (v0,v1) = q[co]*(q[po], q[po+4]); predicated fixup when
// e.y != 0: v1 = q[e.y.a]*q[e.y.b].
__device__ __forceinline__ uint32_t afragP(uint32_t qr, uint2 e) {
    float cmn, p0, p1, v1;
    const uint32_t po = qr + (e.x >> 16);
    asm("ld.shared.f32 %0, [%1];" : "=f"(cmn) : "r"(qr + (e.x & 0xFFFFu)));
    asm("ld.shared.f32 %0, [%1];" : "=f"(p0) : "r"(po));
    asm("ld.shared.f32 %0, [%1];" : "=f"(p1) : "r"(po + 4u));
    const float v0 = cmn * p0;
    asm("{ .reg .pred p; .reg .f32 xa, xb;\n\t"
        "setp.ne.u32 p, %1, 0;\n\t"
        "mul.f32 %0, %2, %3;\n\t"
        "@p ld.shared.f32 xa, [%4];\n\t"
        "@p ld.shared.f32 xb, [%5];\n\t"
        "@p mul.f32 %0, xa, xb;\n\t}"
        : "=f"(v1)
        : "r"(e.y), "f"(cmn), "f"(p1),
          "r"(qr + (e.y & 0xFFFCu)), "r"(qr + (e.y >> 16)));
    return packH2(v0, v1);
}

__device__ __forceinline__ void featAB(int F, int& a, int& b) {
    if (F == 0) { a = 32; b = 32; }
    else if (F < 33) { a = F - 1; b = 32; }
    else if (F < FTOT) {
        int p = F - 33, f1 = 0;
        while (p >= 32 - f1) { p -= 32 - f1; ++f1; }
        a = f1; b = f1 + p;
    } else { a = 33; b = 33; }
}
__global__ void initTab() {
    int F = blockIdx.x * 256 + threadIdx.x;
    if (F < 640) {
        int a, b; featAB(F, a, b);
        float w = 0.0f;
        if (F < FTOT) w = (F < 33) ? 1.0f : ((a == b) ? 0.5f : 1.0f);
        g_ptab4[F] = (uint32_t)(a * 4) | ((uint32_t)(b * 4) << 16);
        g_wtab[F] = w;
    }
    if (F < 320) {
        int a0, b0, a1, b1;
        featAB(2 * F, a0, b0);
        featAB(2 * F + 1, a1, b1);
        uint2 e;
        if (a0 == 33 && a1 == 33) {                 // pad-pad: po+4 -> col34 = 0
            e.x = (uint32_t)(33 * 4) | ((uint32_t)(33 * 4) << 16); e.y = 0;
        } else if (a1 == a0 && b1 == b0 + 1) {      // common a, b adjacent
            e.x = (uint32_t)(a0 * 4) | ((uint32_t)(b0 * 4) << 16); e.y = 0;
        } else if (b1 == b0 && a1 == a0 + 1) {      // common b, a adjacent
            e.x = (uint32_t)(b0 * 4) | ((uint32_t)(a0 * 4) << 16); e.y = 0;
        } else {                                    // boundary pair: fixup v1
            e.x = (uint32_t)(a0 * 4) | ((uint32_t)(b0 * 4) << 16);
            e.y = ((uint32_t)(a1 * 4) | 1u) | ((uint32_t)(b1 * 4) << 16);
        }
        g_ptab2[F] = e;
    }
}

// ---------------------------------------------------------------- phase 1
__global__ __launch_bounds__(256, 4) void ph1(const float* __restrict__ k,
                                              const float* __restrict__ v) {
    __shared__ __align__(16) char sm[2 * 64 * KSTR + 2 * BHALF];
    const int OFF_B = 2 * 64 * KSTR;
    const int bh = blockIdx.x, ft = blockIdx.y, nh = blockIdx.z;
    const int tid = threadIdx.x, wid = tid >> 5, lane = tid & 31;
    const uint32_t smb = smem_u32(sm);

    const float* kb = k + (size_t)bh * NSEQ * DD;
    const float* vb = v + (size_t)bh * NSEQ * DD;

    const int F1 = ft * 128 + wid * 16 + (lane >> 2);
    const uint32_t p1 = g_ptab4[F1], p2 = g_ptab4[F1 + 8];
    const float w1 = g_wtab[F1], w2 = g_wtab[F1 + 8];
    const uint32_t ao1 = p1 & 0xFFFFu, bo1 = p1 >> 16;
    const uint32_t ao2 = p2 & 0xFFFFu, bo2 = p2 >> 16;

    if (tid < 128) {
        float* r = (float*)(sm + (tid >> 6) * 64 * KSTR + (tid & 63) * KSTR);
        r[32] = 1.0f; r[33] = 0.0f; r[34] = 0.0f;
    }

    uint32_t rowp[2];
#pragma unroll
    for (int p = 0; p < 2; ++p) {
        int m = lane >> 3;
        int nb = p * 2 + (m >> 1);
        int e = nb * 8 + (lane & 7);
        rowp[p] = (uint32_t)(e * BSTR + (m & 1) * 16);
    }
    const uint32_t b4c = (lane < 4) ? 0x3C003C00u : 0u;
    const uint32_t b4r[2] = { b4c, b4c };

    float c[5][4] = {};
    const int c0b = (lane & 3) * 2;
    const int NC = (NSEQ / NPART) / 64;

    for (int cc = 0; cc < NC; ++cc) {
        const int buf = cc & 1;
        const int n0 = nh * (NSEQ / NPART) + cc * 64;
        const uint32_t ktb = smb + buf * 64 * KSTR;

        {
            int i2 = tid;
#pragma unroll
            for (int it = 0; it < 2; ++it, i2 += 256) {
                int rr = i2 >> 3, c4 = (i2 & 7) * 4;
                float4 t = *(const float4*)(kb + (size_t)(n0 + rr) * DD + c4);
                float* d = (float*)(sm + buf * 64 * KSTR + rr * KSTR) + c4;
                d[0] = t.x; d[1] = t.y; d[2] = t.z; d[3] = t.w;
            }
        }
#pragma unroll
        for (int it = 0; it < 4; ++it) {
            int i = it * 256 + tid;
            int np = i >> 5, e = i & 31;
            float v0 = vb[(size_t)(n0 + 2 * np) * DD + e];
            float v1 = vb[(size_t)(n0 + 2 * np) * DD + DD + e];
            *(uint32_t*)(sm + OFF_B + buf * BHALF + e * BSTR + np * 4) = packH2(v0, v1);
        }
        __syncthreads();

        const uint32_t bbB = smb + OFF_B + buf * BHALF;
#pragma unroll
        for (int ks = 0; ks < 4; ++ks) {
            const int c0 = ks * 16 + c0b;
            uint32_t ah[4];
            {
                const uint32_t pr0 = ktb + (uint32_t)(c0 * KSTR);
                const uint32_t pr1 = pr0 + KSTR;
                const uint32_t pr8 = pr0 + 8 * KSTR;
                const uint32_t pr9 = pr8 + KSTR;
                ah[0] = packH2(w1 * prod2(pr0, ao1, bo1), w1 * prod2(pr1, ao1, bo1));
                ah[2] = packH2(w1 * prod2(pr8, ao1, bo1), w1 * prod2(pr9, ao1, bo1));
                ah[1] = packH2(w2 * prod2(pr0, ao2, bo2), w2 * prod2(pr1, ao2, bo2));
                ah[3] = packH2(w2 * prod2(pr8, ao2, bo2), w2 * prod2(pr9, ao2, bo2));
            }
            uint32_t b01[4], b23[4];
            ldm4(b01, bbB + rowp[0] + ks * 32);
            ldm4(b23, bbB + rowp[1] + ks * 32);
            mmaH(c[0], ah, b01);
            mmaH(c[1], ah, b01 + 2);
            mmaH(c[2], ah, b23);
            mmaH(c[3], ah, b23 + 2);
            mmaH(c[4], ah, b4r);
        }
    }

    float* dst = g_M3p + (size_t)nh * (NBH * ER * FPAD) + (size_t)bh * ER * FPAD;
    const int Fg = F1;
#pragma unroll
    for (int nb = 0; nb < 5; ++nb) {
        const int e = nb * 8 + (lane & 3) * 2;
        if (nb < 4) {
            if (Fg < FTOT) {
                dst[(size_t)e * FPAD + Fg] = c[nb][0];
                dst[(size_t)(e + 1) * FPAD + Fg] = c[nb][1];
            }
            if (Fg + 8 < FTOT) {
                dst[(size_t)e * FPAD + Fg + 8] = c[nb][2];
                dst[(size_t)(e + 1) * FPAD + Fg + 8] = c[nb][3];
            }
        } else if ((lane & 3) == 0) {
            if (Fg < FTOT)     dst[(size_t)32 * FPAD + Fg] = c[4][0];
            if (Fg + 8 < FTOT) dst[(size_t)32 * FPAD + Fg + 8] = c[4][2];
        }
    }
}

// ---------------------------------------------------------------- combine
__global__ void combineM3() {
    const size_t S = (size_t)NBH * ER * FPAD;
    size_t i = (size_t)blockIdx.x * 256 + threadIdx.x;
    float s = 0.0f;
#pragma unroll
    for (int p = 0; p < NPART; ++p) s += g_M3p[p * S + i];
    g_M3s[i] = s;
}

// ---------------------------------------------------------------- frag
__global__ void fragM3() {
    int i = blockIdx.x * 256 + threadIdx.x;
    int lane = i & 31;
    int nb = (i >> 5) % 5;
    int ks = (i / 160) % 36;
    int bh = i / 5760;
    int e = nb * 8 + (lane >> 2);
    int F0 = ks * 16 + 2 * (lane & 3);
    float vals[4];
    const int Fs[4] = {F0, F0 + 1, F0 + 8, F0 + 9};
#pragma unroll
    for (int t = 0; t < 4; ++t) {
        float s = 0.0f;
        if (e <= 32 && Fs[t] < FTOT)
            s = g_M3s[(size_t)(bh * ER + e) * FPAD + Fs[t]];
        vals[t] = s;
    }
    uint2 w;
    w.x = packH2(vals[0], vals[1]);
    w.y = packH2(vals[2], vals[3]);
    g_M3frag[i] = w;
}

// ---------------------------------------------------------------- phase 2
__global__ __launch_bounds__(256, 4) void ph2(const float* __restrict__ q,
                                              float* __restrict__ out) {
    __shared__ __align__(16) char sm[256 * KSTR + 2560];
    const int OFF_TAB = 256 * KSTR;
    const int bh = blockIdx.x, nt = blockIdx.y;
    const int tid = threadIdx.x, wid = tid >> 5, lane = tid & 31;
    const uint32_t smb = smem_u32(sm);

    {
        const float4* qb4 = (const float4*)(q + ((size_t)bh * NSEQ + nt * 256) * DD);
        int i2 = tid;
#pragma unroll
        for (int it = 0; it < 8; ++it, i2 += 256) {
            int rr = i2 >> 3, c4 = (i2 & 7) * 4;
            float4 t = qb4[i2];
            float* d = (float*)(sm + rr * KSTR) + c4;
            d[0] = t.x; d[1] = t.y; d[2] = t.z; d[3] = t.w;
        }
        {
            float* r = (float*)(sm + tid * KSTR);
            r[32] = 1.0f; r[33] = 0.0f; r[34] = 0.0f;
        }
        for (int i = tid; i < 640; i += 256)
            *(uint32_t*)(sm + OFF_TAB + i * 4) = ((const uint32_t*)g_ptab2)[i];
    }
    __syncthreads();

    const uint32_t q1 = smb + (uint32_t)((wid * 32 + (lane >> 2)) * KSTR);
    const uint2* frag = g_M3frag + (size_t)bh * (36 * 5 * 32) + lane;

    float c[2][5][4] = {};

#pragma unroll 2
    for (int ks = 0; ks < 36; ++ks) {
        const uint2* fb = frag + ks * (5 * 32);
        uint2 b0 = __ldg(fb);
        uint2 b1 = __ldg(fb + 32);
        uint2 b2 = __ldg(fb + 64);
        uint2 b3 = __ldg(fb + 96);
        uint2 b4 = __ldg(fb + 128);

        const uint32_t tadr = smb + OFF_TAB + (uint32_t)((ks * 8 + (lane & 3)) * 8);
        uint2 ea, eb;
        asm("ld.shared.v2.u32 {%0, %1}, [%2];" : "=r"(ea.x), "=r"(ea.y) : "r"(tadr));
        asm("ld.shared.v2.u32 {%0, %1}, [%2];" : "=r"(eb.x), "=r"(eb.y) : "r"(tadr + 32));

        uint32_t a0[4], a1[4];
        a0[0] = afragP(q1, ea);
        a0[1] = afragP(q1 + 8 * KSTR, ea);
        a0[2] = afragP(q1, eb);
        a0[3] = afragP(q1 + 8 * KSTR, eb);
        a1[0] = afragP(q1 + 16 * KSTR, ea);
        a1[1] = afragP(q1 + 24 * KSTR, ea);
        a1[2] = afragP(q1 + 16 * KSTR, eb);
        a1[3] = afragP(q1 + 24 * KSTR, eb);

        mmaH(c[0][0], a0, (const uint32_t*)&b0);
        mmaH(c[1][0], a1, (const uint32_t*)&b0);
        mmaH(c[0][1], a0, (const uint32_t*)&b1);
        mmaH(c[1][1], a1, (const uint32_t*)&b1);
        mmaH(c[0][2], a0, (const uint32_t*)&b2);
        mmaH(c[1][2], a1, (const uint32_t*)&b2);
        mmaH(c[0][3], a0, (const uint32_t*)&b3);
        mmaH(c[1][3], a1, (const uint32_t*)&b3);
        mmaH(c[0][4], a0, (const uint32_t*)&b4);
        mmaH(c[1][4], a1, (const uint32_t*)&b4);
    }

#pragma unroll
    for (int s = 0; s < 2; ++s) {
        const float dl = __shfl_sync(0xFFFFFFFFu, c[s][4][0], lane & ~3);
        const float dh = __shfl_sync(0xFFFFFFFFu, c[s][4][2], lane & ~3);
        const float il = 1.0f / dl, ih = 1.0f / dh;
        const int row = nt * 256 + wid * 32 + s * 16 + (lane >> 2);
        float* ob = out + ((size_t)bh * NSEQ + row) * DD;
#pragma unroll
        for (int nb = 0; nb < 4; ++nb) {
            const int e = nb * 8 + (lane & 3) * 2;
            float2 lo2 = { c[s][nb][0] * il, c[s][nb][1] * il };
            float2 hi2 = { c[s][nb][2] * ih, c[s][nb][3] * ih };
            *(float2*)(ob + e) = lo2;
            *(float2*)(ob + 8 * DD + e) = hi2;
        }
    }
}

// ---------------------------------------------------------------- launch
extern "C" void kernel_launch(void* const* d_in, const int* in_sizes, int n_in,
                              void* d_out, int out_size) {
    const float* q = (const float*)d_in[0];
    const float* k = (const float*)d_in[1];
    const float* v = (const float*)d_in[2];
    float* out = (float*)d_out;
    (void)in_sizes; (void)n_in; (void)out_size;

    initTab<<<3, 256>>>();
    ph1<<<dim3(NBH, 5, NPART), 256>>>(k, v);
    combineM3<<<(NBH * ER * FPAD) / 256, 256>>>();
    fragM3<<<(NBH * 36 * 5 * 32) / 256, 256>>>();
    ph2<<<dim3(NBH, 16), 256>>>(q, out);
}

// round 16
// speedup vs baseline: 1.5820x; 1.5820x over previous
#include <cuda_runtime.h>
#include <cuda_fp16.h>
#include <cstdint>

// FAST attention (p=2 Taylor linear attention) as two unified feature GEMMs
// on HMMA fp16 (mma.sync m16n8k16, fp32 accum).  [R12 proven-best structure]
//   Phi[n,F]: F=0 -> 1, F=1..32 -> x_d, F=33..560 -> pair products
//   Phase 1: M3[F,e] = sum_n PhiK_w[n,F] * Vaug[n,e]   (A fp16 regs from
//            row-major k-stage; B fp16 smem + ldmatrix; ones-row constant)
//   combine: 8 n-partials -> one fp32 M3 (coalesced)
//   frag:    M3 -> pre-swizzled per-lane fp16 mma B-fragments
//   Phase 2: D[n,e]  = sum_F PhiQ[n,F] * M3[F,e]; out = D[:,0:32]/D[:,32]
//            (B per-lane from gmem fragments; no mainloop syncs)

#define NBH   32
#define NSEQ  4096
#define DD    32
#define FTOT  561
#define FPAD  576
#define ER    33
#define NPART 8

#define KSTR  140          // staged fp32 tile row stride bytes (35 floats)
#define BSTR  144          // ph1 B row stride bytes (64 halves + pad)
#define BROWS 32           // e = 0..31 only (ones-row handled as constant)
#define BHALF (BROWS * BSTR)          // 4608

__device__ uint32_t g_ptab4[640];     // (a*4) | (b*4 << 16); pad -> col 33
__device__ float    g_wtab[640];      // ph1 row weight, pad 0
__device__ float    g_M3p[NPART * NBH * ER * FPAD];
__device__ float    g_M3s[NBH * ER * FPAD];
__device__ uint2    g_M3frag[NBH * 36 * 5 * 32];   // [bh][ks][nb][lane]

// ---------------------------------------------------------------- helpers
__device__ __forceinline__ uint32_t smem_u32(const void* p) {
    uint32_t a;
    asm("{ .reg .u64 t; cvta.to.shared.u64 t, %1; cvt.u32.u64 %0, t; }" : "=r"(a) : "l"(p));
    return a;
}
__device__ __forceinline__ uint32_t packH2(float v0, float v1) {
    uint32_t r;
    asm("cvt.rn.f16x2.f32 %0, %1, %2;" : "=r"(r) : "f"(v1), "f"(v0));  // lo=v0
    return r;
}
__device__ __forceinline__ void ldm4(uint32_t b[4], uint32_t addr) {
    asm volatile("ldmatrix.sync.aligned.m8n8.x4.shared.b16 {%0,%1,%2,%3}, [%4];"
                 : "=r"(b[0]), "=r"(b[1]), "=r"(b[2]), "=r"(b[3]) : "r"(addr));
}
__device__ __forceinline__ void mmaH(float c[4], const uint32_t a[4], const uint32_t b[2]) {
    asm volatile("mma.sync.aligned.m16n8k16.row.col.f32.f16.f16.f32 "
                 "{%0,%1,%2,%3}, {%4,%5,%6,%7}, {%8,%9}, {%0,%1,%2,%3};"
                 : "+f"(c[0]), "+f"(c[1]), "+f"(c[2]), "+f"(c[3])
                 : "r"(a[0]), "r"(a[1]), "r"(a[2]), "r"(a[3]), "r"(b[0]), "r"(b[1]));
}
__device__ __forceinline__ float prod2(uint32_t pr, uint32_t ao, uint32_t bo) {
    float x, y;
    asm("ld.shared.f32 %0, [%1];" : "=f"(x) : "r"(pr + ao));
    asm("ld.shared.f32 %0, [%1];" : "=f"(y) : "r"(pr + bo));
    return x * y;
}
__device__ __forceinline__ uint32_t afrag(uint32_t qr, uint32_t ta, uint32_t tb) {
    float v0 = prod2(qr, ta & 0xFFFFu, ta >> 16);
    float v1 = prod2(qr, tb & 0xFFFFu, tb >> 16);
    return packH2(v0, v1);
}

// ---------------------------------------------------------------- init table
__global__ void initTab() {
    int F = blockIdx.x * 256 + threadIdx.x;
    if (F >= 640) return;
    int a = 33, b = 33;
    float w = 0.0f;
    if (F == 0) { a = 32; b = 32; w = 1.0f; }
    else if (F < 33) { a = F - 1; b = 32; w = 1.0f; }
    else if (F < FTOT) {
        int p = F - 33, f1 = 0;
        while (p >= 32 - f1) { p -= 32 - f1; ++f1; }
        a = f1; b = f1 + p;
        w = (a == b) ? 0.5f : 1.0f;
    }
    g_ptab4[F] = (uint32_t)(a * 4) | ((uint32_t)(b * 4) << 16);
    g_wtab[F] = w;
}

// ---------------------------------------------------------------- phase 1
// grid (NBH, 5 F-tiles, NPART n-slices). A (PhiK_w) single fp16 in regs from
// row-major k-stage; B = Vaug^T single fp16 in smem (rows 0..31) + constant
// ones-fragment for the e=32 row; double-buffered; one sync per chunk.
__global__ __launch_bounds__(256, 4) void ph1(const float* __restrict__ k,
                                              const float* __restrict__ v) {
    __shared__ __align__(16) char sm[2 * 64 * KSTR + 2 * BHALF];   // 27136 B
    const int OFF_B = 2 * 64 * KSTR;                               // 17920
    const int bh = blockIdx.x, ft = blockIdx.y, nh = blockIdx.z;
    const int tid = threadIdx.x, wid = tid >> 5, lane = tid & 31;
    const uint32_t smb = smem_u32(sm);

    const float* kb = k + (size_t)bh * NSEQ * DD;
    const float* vb = v + (size_t)bh * NSEQ * DD;

    const int F1 = ft * 128 + wid * 16 + (lane >> 2);
    const uint32_t p1 = g_ptab4[F1], p2 = g_ptab4[F1 + 8];
    const float w1 = g_wtab[F1], w2 = g_wtab[F1 + 8];
    const uint32_t ao1 = p1 & 0xFFFFu, bo1 = p1 >> 16;
    const uint32_t ao2 = p2 & 0xFFFFu, bo2 = p2 >> 16;

    // init: kt cols 32..34 = {1,0,0} in both buffers
    if (tid < 128) {
        float* r = (float*)(sm + (tid >> 6) * 64 * KSTR + (tid & 63) * KSTR);
        r[32] = 1.0f; r[33] = 0.0f; r[34] = 0.0f;
    }

    // B fragment offsets: two ldm4 pairs (nb0/1, nb2/3); nb4 is constant
    uint32_t rowp[2];
#pragma unroll
    for (int p = 0; p < 2; ++p) {
        int m = lane >> 3;
        int nb = p * 2 + (m >> 1);
        int e = nb * 8 + (lane & 7);              // <= 31
        rowp[p] = (uint32_t)(e * BSTR + (m & 1) * 16);
    }
    const uint32_t b4c = (lane < 4) ? 0x3C003C00u : 0u;
    const uint32_t b4r[2] = { b4c, b4c };

    float c[5][4] = {};
    const int c0b = (lane & 3) * 2;
    const int NC = (NSEQ / NPART) / 64;                     // 8 chunks

    for (int cc = 0; cc < NC; ++cc) {
        const int buf = cc & 1;
        const int n0 = nh * (NSEQ / NPART) + cc * 64;
        const uint32_t ktb = smb + buf * 64 * KSTR;

        // stage k tile [64][32] fp32 (row-major)
        {
            int i2 = tid;
#pragma unroll
            for (int it = 0; it < 2; ++it, i2 += 256) {
                int rr = i2 >> 3, c4 = (i2 & 7) * 4;
                float4 t = *(const float4*)(kb + (size_t)(n0 + rr) * DD + c4);
                float* d = (float*)(sm + buf * 64 * KSTR + rr * KSTR) + c4;
                d[0] = t.x; d[1] = t.y; d[2] = t.z; d[3] = t.w;
            }
        }
        // build B rows 0..31 (Vaug^T, single fp16)
#pragma unroll
        for (int it = 0; it < 4; ++it) {
            int i = it * 256 + tid;
            int np = i >> 5, e = i & 31;
            float v0 = vb[(size_t)(n0 + 2 * np) * DD + e];
            float v1 = vb[(size_t)(n0 + 2 * np) * DD + DD + e];
            *(uint32_t*)(sm + OFF_B + buf * BHALF + e * BSTR + np * 4) = packH2(v0, v1);
        }
        __syncthreads();

        const uint32_t bbB = smb + OFF_B + buf * BHALF;
#pragma unroll
        for (int ks = 0; ks < 4; ++ks) {
            const int c0 = ks * 16 + c0b;
            uint32_t ah[4];
            {
                const uint32_t pr0 = ktb + (uint32_t)(c0 * KSTR);
                const uint32_t pr1 = pr0 + KSTR;
                const uint32_t pr8 = pr0 + 8 * KSTR;
                const uint32_t pr9 = pr8 + KSTR;
                ah[0] = packH2(w1 * prod2(pr0, ao1, bo1), w1 * prod2(pr1, ao1, bo1));
                ah[2] = packH2(w1 * prod2(pr8, ao1, bo1), w1 * prod2(pr9, ao1, bo1));
                ah[1] = packH2(w2 * prod2(pr0, ao2, bo2), w2 * prod2(pr1, ao2, bo2));
                ah[3] = packH2(w2 * prod2(pr8, ao2, bo2), w2 * prod2(pr9, ao2, bo2));
            }
            uint32_t b01[4], b23[4];
            ldm4(b01, bbB + rowp[0] + ks * 32);
            ldm4(b23, bbB + rowp[1] + ks * 32);
            mmaH(c[0], ah, b01);
            mmaH(c[1], ah, b01 + 2);
            mmaH(c[2], ah, b23);
            mmaH(c[3], ah, b23 + 2);
            mmaH(c[4], ah, b4r);
        }
    }

    // epilogue: NPART disjoint partial buffers, no atomics
    float* dst = g_M3p + (size_t)nh * (NBH * ER * FPAD) + (size_t)bh * ER * FPAD;
    const int Fg = F1;
#pragma unroll
    for (int nb = 0; nb < 5; ++nb) {
        const int e = nb * 8 + (lane & 3) * 2;
        if (nb < 4) {
            if (Fg < FTOT) {
                dst[(size_t)e * FPAD + Fg] = c[nb][0];
                dst[(size_t)(e + 1) * FPAD + Fg] = c[nb][1];
            }
            if (Fg + 8 < FTOT) {
                dst[(size_t)e * FPAD + Fg + 8] = c[nb][2];
                dst[(size_t)(e + 1) * FPAD + Fg + 8] = c[nb][3];
            }
        } else if ((lane & 3) == 0) {
            if (Fg < FTOT)     dst[(size_t)32 * FPAD + Fg] = c[4][0];
            if (Fg + 8 < FTOT) dst[(size_t)32 * FPAD + Fg + 8] = c[4][2];
        }
    }
}

// ---------------------------------------------------------------- combine
// Coalesced 8-partial reduction into one fp32 M3 buffer.
__global__ void combineM3() {
    const size_t S = (size_t)NBH * ER * FPAD;
    size_t i = (size_t)blockIdx.x * 256 + threadIdx.x;
    float s = 0.0f;
#pragma unroll
    for (int p = 0; p < NPART; ++p) s += g_M3p[p * S + i];
    g_M3s[i] = s;
}

// ---------------------------------------------------------------- frag
// word(bh,ks,nb,lane) = { (M3[e][F0],M3[e][F0+1]), (M3[e][F0+8],M3[e][F0+9]) },
// e = nb*8+lane/4, F0 = ks*16+2*(lane%4).
__global__ void fragM3() {
    int i = blockIdx.x * 256 + threadIdx.x;                // < 184320
    int lane = i & 31;
    int nb = (i >> 5) % 5;
    int ks = (i / 160) % 36;
    int bh = i / 5760;
    int e = nb * 8 + (lane >> 2);
    int F0 = ks * 16 + 2 * (lane & 3);
    float vals[4];
    const int Fs[4] = {F0, F0 + 1, F0 + 8, F0 + 9};
#pragma unroll
    for (int t = 0; t < 4; ++t) {
        float s = 0.0f;
        if (e <= 32 && Fs[t] < FTOT)
            s = g_M3s[(size_t)(bh * ER + e) * FPAD + Fs[t]];
        vals[t] = s;
    }
    uint2 w;
    w.x = packH2(vals[0], vals[1]);
    w.y = packH2(vals[2], vals[3]);
    g_M3frag[i] = w;
}

// ---------------------------------------------------------------- phase 2
// grid (NBH, 16 n-tiles of 256 rows). 8 warps x 32 rows (2 A-sets). B per
// lane from g_M3frag via coalesced LDG.64 — no B smem, no mainloop syncs.
__global__ __launch_bounds__(256, 4) void ph2(const float* __restrict__ q,
                                              float* __restrict__ out) {
    __shared__ __align__(16) char sm[256 * KSTR + 2560];   // 38400 B
    const int OFF_TAB = 256 * KSTR;                        // 35840
    const int bh = blockIdx.x, nt = blockIdx.y;
    const int tid = threadIdx.x, wid = tid >> 5, lane = tid & 31;
    const uint32_t smb = smem_u32(sm);

    // stage q tile [256][32] + cols 32..34 = {1,0,0}; copy table
    {
        const float4* qb4 = (const float4*)(q + ((size_t)bh * NSEQ + nt * 256) * DD);
        int i2 = tid;
#pragma unroll
        for (int it = 0; it < 8; ++it, i2 += 256) {
            int rr = i2 >> 3, c4 = (i2 & 7) * 4;
            float4 t = qb4[i2];
            float* d = (float*)(sm + rr * KSTR) + c4;
            d[0] = t.x; d[1] = t.y; d[2] = t.z; d[3] = t.w;
        }
        {
            float* r = (float*)(sm + tid * KSTR);
            r[32] = 1.0f; r[33] = 0.0f; r[34] = 0.0f;
        }
        for (int i = tid; i < 640; i += 256)
            *(uint32_t*)(sm + OFF_TAB + i * 4) = g_ptab4[i];
    }
    __syncthreads();

    const uint32_t q1 = smb + (uint32_t)((wid * 32 + (lane >> 2)) * KSTR);
    const int c0b = (lane & 3) * 2;
    const uint2* frag = g_M3frag + (size_t)bh * (36 * 5 * 32) + lane;

    float c[2][5][4] = {};

#pragma unroll 2
    for (int ks = 0; ks < 36; ++ks) {
        // B fragments straight from gmem (L2-resident), fully coalesced
        const uint2* fb = frag + ks * (5 * 32);
        uint2 b0 = __ldg(fb);
        uint2 b1 = __ldg(fb + 32);
        uint2 b2 = __ldg(fb + 64);
        uint2 b3 = __ldg(fb + 96);
        uint2 b4 = __ldg(fb + 128);

        const int c0 = ks * 16 + c0b;
        const uint2 tA = *(const uint2*)(sm + OFF_TAB + c0 * 4);       // t0,t1
        const uint2 tB = *(const uint2*)(sm + OFF_TAB + c0 * 4 + 32);  // t8,t9

        uint32_t a0[4], a1[4];
        a0[0] = afrag(q1, tA.x, tA.y);
        a0[1] = afrag(q1 + 8 * KSTR, tA.x, tA.y);
        a0[2] = afrag(q1, tB.x, tB.y);
        a0[3] = afrag(q1 + 8 * KSTR, tB.x, tB.y);
        a1[0] = afrag(q1 + 16 * KSTR, tA.x, tA.y);
        a1[1] = afrag(q1 + 24 * KSTR, tA.x, tA.y);
        a1[2] = afrag(q1 + 16 * KSTR, tB.x, tB.y);
        a1[3] = afrag(q1 + 24 * KSTR, tB.x, tB.y);

        mmaH(c[0][0], a0, (const uint32_t*)&b0);
        mmaH(c[1][0], a1, (const uint32_t*)&b0);
        mmaH(c[0][1], a0, (const uint32_t*)&b1);
        mmaH(c[1][1], a1, (const uint32_t*)&b1);
        mmaH(c[0][2], a0, (const uint32_t*)&b2);
        mmaH(c[1][2], a1, (const uint32_t*)&b2);
        mmaH(c[0][3], a0, (const uint32_t*)&b3);
        mmaH(c[1][3], a1, (const uint32_t*)&b3);
        mmaH(c[0][4], a0, (const uint32_t*)&b4);
        mmaH(c[1][4], a1, (const uint32_t*)&b4);
    }

    // epilogue per A-set: divide by den (e=32 -> nb4 col 0, lanes l%4==0)
#pragma unroll
    for (int s = 0; s < 2; ++s) {
        const float dl = __shfl_sync(0xFFFFFFFFu, c[s][4][0], lane & ~3);
        const float dh = __shfl_sync(0xFFFFFFFFu, c[s][4][2], lane & ~3);
        const float il = 1.0f / dl, ih = 1.0f / dh;
        const int row = nt * 256 + wid * 32 + s * 16 + (lane >> 2);
        float* ob = out + ((size_t)bh * NSEQ + row) * DD;
#pragma unroll
        for (int nb = 0; nb < 4; ++nb) {
            const int e = nb * 8 + (lane & 3) * 2;
            float2 lo2 = { c[s][nb][0] * il, c[s][nb][1] * il };
            float2 hi2 = { c[s][nb][2] * ih, c[s][nb][3] * ih };
            *(float2*)(ob + e) = lo2;
            *(float2*)(ob + 8 * DD + e) = hi2;
        }
    }
}

// ---------------------------------------------------------------- launch
extern "C" void kernel_launch(void* const* d_in, const int* in_sizes, int n_in,
                              void* d_out, int out_size) {
    const float* q = (const float*)d_in[0];
    const float* k = (const float*)d_in[1];
    const float* v = (const float*)d_in[2];
    float* out = (float*)d_out;
    (void)in_sizes; (void)n_in; (void)out_size;

    initTab<<<3, 256>>>();
    ph1<<<dim3(NBH, 5, NPART), 256>>>(k, v);
    combineM3<<<(NBH * ER * FPAD) / 256, 256>>>();
    fragM3<<<(NBH * 36 * 5 * 32) / 256, 256>>>();
    ph2<<<dim3(NBH, 16), 256>>>(q, out);
}